// round 12
// baseline (speedup 1.0000x reference)
#include <cuda_runtime.h>

// Problem constants (fixed: N=4, M=8192, D=64, k=16)
#define NB 4
#define MP 8192
#define DD 64
#define KNN 16
#define TM 256
#define TN 64
#define NTILES (MP / TN)        // 128
#define NTHREADS 512
#define NEDGES (NB * MP * KNN)  // 524288

#define PA 260   // At pitch (floats)
#define PB2 80   // Bt2 pitch (ull): 64 cols padded n+(n>>2) -> max 78
#define PD 67    // Dt pitch

// shared layout (float offsets)
#define SM_AT  0                            // 64 x 260 fl = 16640
#define SM_BT2 (DD * PA)                    // 64 x 80 ull = 10240 fl
#define SM_DT  (SM_BT2 + DD * PB2 * 2)      // 256 x 67 fl = 17152
#define SM_X2R (SM_DT + TM * PD)            // 256 fl
#define SMEM_FLOATS (SM_X2R + TM)           // 44288
#define SMEM_BYTES  (SMEM_FLOATS * 4)       // 177,152 B -> 1 CTA/SM, 16 warps

typedef unsigned long long ull;

__device__ float g_x2[NB * MP];             // precomputed squared norms (128 KB)

__device__ __forceinline__ ull ffma2(ull a, ull b, ull c) {
    ull d;
    asm("fma.rn.f32x2 %0, %1, %2, %3;" : "=l"(d) : "l"(a), "l"(b), "l"(c));
    return d;
}
__device__ __forceinline__ ull splat2(float v) {
    ull d;
    unsigned u = __float_as_uint(v);
    asm("mov.b64 %0, {%1, %1};" : "=l"(d) : "r"(u));
    return d;
}
__device__ __forceinline__ float lane_lo(ull v) { return __uint_as_float((unsigned)v); }
__device__ __forceinline__ float lane_hi(ull v) { return __uint_as_float((unsigned)(v >> 32)); }

// ---- pre-kernel: squared norms, same fma order as before (bit-identical) ----
__global__ __launch_bounds__(256)
void norms_kernel(const float* __restrict__ x) {
    int i = blockIdx.x * 256 + threadIdx.x;          // 0..32767
    const float4* p = reinterpret_cast<const float4*>(x + (size_t)i * DD);
    float s = 0.f;
    #pragma unroll
    for (int q = 0; q < 16; ++q) {
        float4 v = p[q];
        s = fmaf(v.x, v.x, s); s = fmaf(v.y, v.y, s);
        s = fmaf(v.z, v.z, s); s = fmaf(v.w, v.w, s);
    }
    g_x2[i] = s;
}

__global__ __launch_bounds__(NTHREADS, 1)
void knn_topk_kernel(const float* __restrict__ x,
                     float* __restrict__ out,
                     int write_dst) {
    extern __shared__ float sm[];
    float* At  = sm + SM_AT;                 // [64][PA]  At[d][m]
    ull*   Bt2 = (ull*)(sm + SM_BT2);        // [64][PB2] dup-packed b
    float* Dt  = sm + SM_DT;                 // [256][PD]
    float* x2r = sm + SM_X2R;

    const int tid   = threadIdx.x;
    const int batch = blockIdx.x >> 5;       // 32 row-tiles per batch
    const int rtile = blockIdx.x & 31;
    const float* xb = x + (size_t)batch * MP * DD;
    const float* nb = g_x2 + batch * MP;
    const int row0  = rtile * TM;

    // ---- Prologue: A tile (256 x 64) transposed to d-major ----
    #pragma unroll
    for (int it = 0; it < 8; ++it) {
        int idx = it * NTHREADS + tid;       // 0..4095
        int m   = idx & 255;
        int d4  = idx >> 8;                  // 0..15
        float4 v = *reinterpret_cast<const float4*>(xb + (size_t)(row0 + m) * DD + d4 * 4);
        At[(d4 * 4 + 0) * PA + m] = v.x;
        At[(d4 * 4 + 1) * PA + m] = v.y;
        At[(d4 * 4 + 2) * PA + m] = v.z;
        At[(d4 * 4 + 3) * PA + m] = v.w;
    }
    if (tid < TM) x2r[tid] = nb[row0 + tid];   // precomputed row norms

    // ---- B tile 0: load regs, store duplicated ----
    float4 pf[2];
    #pragma unroll
    for (int it = 0; it < 2; ++it) {
        int idx = it * NTHREADS + tid;       // 0..1023
        int n   = idx & 63;
        int d4  = idx >> 6;
        pf[it] = *reinterpret_cast<const float4*>(xb + (size_t)n * DD + d4 * 4);
    }
    #pragma unroll
    for (int it = 0; it < 2; ++it) {
        int idx = it * NTHREADS + tid;
        int n   = idx & 63;
        int d4  = idx >> 6;
        int np  = n + (n >> 2);              // padded column
        Bt2[(d4 * 4 + 0) * PB2 + np] = splat2(pf[it].x);
        Bt2[(d4 * 4 + 1) * PB2 + np] = splat2(pf[it].y);
        Bt2[(d4 * 4 + 2) * PB2 + np] = splat2(pf[it].z);
        Bt2[(d4 * 4 + 3) * PB2 + np] = splat2(pf[it].w);
    }
    __syncthreads();

    const int ty = tid >> 4;          // 0..31
    const int tx = tid & 15;          // 0..15
    const int r0 = ty * 8;
    const int c0 = tx * 4;
    const int bo = 5 * tx;            // padded offset of c0 in Bt2 row

    // scan: 2 threads per row, 32 cols each
    const int srow = tid & 255;
    const int sh   = tid >> 8;
    const float* drow = &Dt[srow * PD + sh * 32];

    float best[KNN];
    int   bidx[KNN];
    #pragma unroll
    for (int i = 0; i < KNN; ++i) { best[i] = __int_as_float(0x7f800000); bidx[i] = 0; }

    for (int ct = 0; ct < NTILES; ++ct) {
        // ========== P1: scan(ct-1) | x2c LDG | prefetch | GEMM(ct) ==========
        if (ct > 0) {
            const int cbase = (ct - 1) * TN + sh * 32;
            float b15 = best[KNN - 1];
            #pragma unroll 4
            for (int c = 0; c < 32; ++c) {
                float v = drow[c];
                if (v < b15) {
                    best[KNN - 1] = v;
                    bidx[KNN - 1] = cbase + c;
                    #pragma unroll
                    for (int j = KNN - 1; j > 0; --j) {
                        if (best[j] < best[j - 1]) {
                            float tv = best[j]; best[j] = best[j - 1]; best[j - 1] = tv;
                            int   ti = bidx[j]; bidx[j] = bidx[j - 1]; bidx[j - 1] = ti;
                        }
                    }
                    b15 = best[KNN - 1];
                }
            }
        }
        // candidate norms for this tile's 4 columns (L2-resident, hidden)
        float4 xc4 = *reinterpret_cast<const float4*>(nb + ct * TN + c0);

        // prefetch next B tile (hidden under GEMM)
        if (ct + 1 < NTILES) {
            const int col0n = (ct + 1) * TN;
            #pragma unroll
            for (int it = 0; it < 2; ++it) {
                int idx = it * NTHREADS + tid;
                int n   = idx & 63;
                int d4  = idx >> 6;
                pf[it] = *reinterpret_cast<const float4*>(xb + (size_t)(col0n + n) * DD + d4 * 4);
            }
        }

        // ---- 256x64x64 GEMM, 8x4 micro-tile, pure f32x2 (no movs in loop) ----
        ull acc[4][4];
        #pragma unroll
        for (int ip = 0; ip < 4; ++ip)
            #pragma unroll
            for (int j = 0; j < 4; ++j) acc[ip][j] = 0ULL;

        #pragma unroll 2
        for (int k = 0; k < DD; ++k) {
            ulonglong2 a01 = *reinterpret_cast<const ulonglong2*>(&At[k * PA + r0]);
            ulonglong2 a23 = *reinterpret_cast<const ulonglong2*>(&At[k * PA + r0 + 4]);
            const ull* bp = Bt2 + k * PB2 + bo;
            ull b0 = bp[0], b1 = bp[1], b2 = bp[2], b3 = bp[3];
            ull ap[4] = {a01.x, a01.y, a23.x, a23.y};
            #pragma unroll
            for (int ip = 0; ip < 4; ++ip) {
                acc[ip][0] = ffma2(ap[ip], b0, acc[ip][0]);
                acc[ip][1] = ffma2(ap[ip], b1, acc[ip][1]);
                acc[ip][2] = ffma2(ap[ip], b2, acc[ip][2]);
                acc[ip][3] = ffma2(ap[ip], b3, acc[ip][3]);
            }
        }
        __syncthreads();   // GEMM reads of Bt2 done

        // ========== P2: epilogue -> Dt | store prefetched Bt2 ===============
        {
            float xc[4] = {xc4.x, xc4.y, xc4.z, xc4.w};
            #pragma unroll
            for (int ip = 0; ip < 4; ++ip) {
                int ra = r0 + ip * 2;
                float xra = x2r[ra], xrb = x2r[ra + 1];
                #pragma unroll
                for (int j = 0; j < 4; ++j) {
                    // t - 2*dot via fma: rounds identically to the reference
                    Dt[ra * PD + c0 + j]       = fmaf(-2.f, lane_lo(acc[ip][j]), xra + xc[j]);
                    Dt[(ra + 1) * PD + c0 + j] = fmaf(-2.f, lane_hi(acc[ip][j]), xrb + xc[j]);
                }
            }
        }
        if (ct + 1 < NTILES) {
            #pragma unroll
            for (int it = 0; it < 2; ++it) {
                int idx = it * NTHREADS + tid;
                int n   = idx & 63;
                int d4  = idx >> 6;
                int np  = n + (n >> 2);
                Bt2[(d4 * 4 + 0) * PB2 + np] = splat2(pf[it].x);
                Bt2[(d4 * 4 + 1) * PB2 + np] = splat2(pf[it].y);
                Bt2[(d4 * 4 + 2) * PB2 + np] = splat2(pf[it].z);
                Bt2[(d4 * 4 + 3) * PB2 + np] = splat2(pf[it].w);
            }
        }
        __syncthreads();
    }

    // ---- final scan (last tile) ----
    {
        const int cbase = (NTILES - 1) * TN + sh * 32;
        float b15 = best[KNN - 1];
        #pragma unroll 4
        for (int c = 0; c < 32; ++c) {
            float v = drow[c];
            if (v < b15) {
                best[KNN - 1] = v;
                bidx[KNN - 1] = cbase + c;
                #pragma unroll
                for (int j = KNN - 1; j > 0; --j) {
                    if (best[j] < best[j - 1]) {
                        float tv = best[j]; best[j] = best[j - 1]; best[j - 1] = tv;
                        int   ti = bidx[j]; bidx[j] = bidx[j - 1]; bidx[j - 1] = ti;
                    }
                }
                b15 = best[KNN - 1];
            }
        }
    }
    __syncthreads();   // everyone done with At -> reuse as merge scratch

    // ---- merge two half-lists per row (stable: ties -> lower index) ----
    #pragma unroll
    for (int j = 0; j < KNN; ++j) {
        At[srow * 32 + sh * KNN + j]                     = best[j];
        ((int*)(At + TM * 32))[srow * 32 + sh * KNN + j] = bidx[j];
    }
    __syncthreads();

    if (tid < TM) {
        const int row = tid;
        const float* v0 = &At[row * 32];
        const float* v1 = &At[row * 32 + KNN];
        const int*   i0 = &((int*)(At + TM * 32))[row * 32];
        const int*   i1 = &((int*)(At + TM * 32))[row * 32 + KNN];
        int p0 = 0, p1 = 0;
        const int gid  = batch * MP + row0 + row;
        const int off  = batch * MP;
        const int base = gid * KNN;
        #pragma unroll
        for (int t = 0; t < KNN; ++t) {
            float a = (p0 < KNN) ? v0[p0] : __int_as_float(0x7f800000);
            float b = (p1 < KNN) ? v1[p1] : __int_as_float(0x7f800000);
            int   ia = (p0 < KNN) ? i0[p0] : 0x7fffffff;
            int   ib = (p1 < KNN) ? i1[p1] : 0x7fffffff;
            bool take0 = (a < b) || (a == b && ia < ib);
            int sel = take0 ? ia : ib;
            if (take0) ++p0; else ++p1;
            out[base + t] = (float)(sel + off);
        }
        if (write_dst) {
            float fgid = (float)gid;
            #pragma unroll
            for (int t = 0; t < KNN; ++t) out[NEDGES + base + t] = fgid;
        }
    }
}

extern "C" void kernel_launch(void* const* d_in, const int* in_sizes, int n_in,
                              void* d_out, int out_size) {
    // Bind x = largest input (robust to ordering and element/byte units).
    const float* x = (const float*)d_in[0];
    long long best_sz = -1;
    for (int i = 0; i < n_in; ++i) {
        if ((long long)in_sizes[i] > best_sz) {
            best_sz = in_sizes[i];
            x = (const float*)d_in[i];
        }
    }
    const int write_dst = (out_size >= 2 * NEDGES);

    norms_kernel<<<NB * MP / 256, 256>>>(x);

    cudaFuncSetAttribute(knn_topk_kernel,
                         cudaFuncAttributeMaxDynamicSharedMemorySize, SMEM_BYTES);
    knn_topk_kernel<<<NB * (MP / TM), NTHREADS, SMEM_BYTES>>>(x, (float*)d_out, write_dst);
}

// round 13
// speedup vs baseline: 1.0975x; 1.0975x over previous
#include <cuda_runtime.h>

// Problem constants (fixed: N=4, M=8192, D=64, k=16)
#define NB 4
#define MP 8192
#define DD 64
#define KNN 16
#define TM 256
#define TN 64
#define NTILES (MP / TN)        // 128
#define NTHREADS 512
#define NEDGES (NB * MP * KNN)  // 524288

#define PA 260   // At pitch (floats)
#define PB 68    // Bt pitch
#define PD 67    // Dt pitch
#define PL 17    // top-k list stride (16 entries + 1 pad)

// shared layout (float offsets)
#define SM_AT   0                           // 64 x 260 = 16640
#define SM_BT   (DD * PA)                   // + 64 x 68 = 4352
#define SM_DT   (SM_BT + DD * PB)           // + 256 x 67 = 17152
#define SM_X2R  (SM_DT + TM * PD)           // + 256
#define SM_X2C  (SM_X2R + TM)               // + 64
#define SM_TOPV (SM_X2C + TN)               // + 512 x 17 = 8704
#define SM_TOPI (SM_TOPV + 2 * TM * PL)     // + 8704
#define SMEM_FLOATS (SM_TOPI + 2 * TM * PL) // 55872
#define SMEM_BYTES  (SMEM_FLOATS * 4)       // 223,488 B -> 1 CTA/SM, 16 warps

typedef unsigned long long ull;

__device__ __forceinline__ ull ffma2(ull a, ull b, ull c) {
    ull d;
    asm("fma.rn.f32x2 %0, %1, %2, %3;" : "=l"(d) : "l"(a), "l"(b), "l"(c));
    return d;
}
__device__ __forceinline__ ull splat2(float v) {
    ull d;
    unsigned u = __float_as_uint(v);
    asm("mov.b64 %0, {%1, %1};" : "=l"(d) : "r"(u));
    return d;
}
__device__ __forceinline__ float lane_lo(ull v) { return __uint_as_float((unsigned)v); }
__device__ __forceinline__ float lane_hi(ull v) { return __uint_as_float((unsigned)(v >> 32)); }

__global__ __launch_bounds__(NTHREADS, 1)
void knn_topk_kernel(const float* __restrict__ x,
                     float* __restrict__ out,
                     int write_dst) {
    extern __shared__ float sm[];
    float* At   = sm + SM_AT;    // [64][PA]  At[d][m], m=0..255
    float* Bt   = sm + SM_BT;    // [64][PB]  Bt[d][n], n=0..63
    float* Dt   = sm + SM_DT;    // [256][PD] d2 tile
    float* x2r  = sm + SM_X2R;
    float* x2c  = sm + SM_X2C;
    float* topv = sm + SM_TOPV;  // 512 lists x 16 (stride 17)
    int*   topi = (int*)(sm + SM_TOPI);

    const int tid   = threadIdx.x;
    const int batch = blockIdx.x >> 5;          // 32 row-tiles per batch
    const int rtile = blockIdx.x & 31;
    const float* xb = x + (size_t)batch * MP * DD;
    const int row0  = rtile * TM;

    // scan: 2 threads per row, 32 cols each; per-thread smem top-16 list
    const int srow = tid & 255;
    const int sh   = tid >> 8;        // 0 or 1
    const float* drow = &Dt[srow * PD + sh * 32];
    float* tv = &topv[(srow * 2 + sh) * PL];
    int*   ti = &topi[(srow * 2 + sh) * PL];

    // init top-16 (own list only)
    #pragma unroll
    for (int j = 0; j < KNN; ++j) { tv[j] = __int_as_float(0x7f800000); ti[j] = 0; }
    float tau = __int_as_float(0x7f800000);

    // ---- Prologue: A tile (256 x 64) transposed to d-major ----
    #pragma unroll
    for (int it = 0; it < 8; ++it) {
        int idx = it * NTHREADS + tid;          // 0..4095
        int m   = idx & 255;
        int d4  = idx >> 8;                     // 0..15
        float4 v = *reinterpret_cast<const float4*>(xb + (size_t)(row0 + m) * DD + d4 * 4);
        At[(d4 * 4 + 0) * PA + m] = v.x;
        At[(d4 * 4 + 1) * PA + m] = v.y;
        At[(d4 * 4 + 2) * PA + m] = v.z;
        At[(d4 * 4 + 3) * PA + m] = v.w;
    }
    // ---- B tile 0: prefetch to regs, store ----
    float4 pf[2];
    #pragma unroll
    for (int it = 0; it < 2; ++it) {
        int idx = it * NTHREADS + tid;          // 0..1023
        int n   = idx & 63;
        int d4  = idx >> 6;
        pf[it] = *reinterpret_cast<const float4*>(xb + (size_t)n * DD + d4 * 4);
    }
    #pragma unroll
    for (int it = 0; it < 2; ++it) {
        int idx = it * NTHREADS + tid;
        int n   = idx & 63;
        int d4  = idx >> 6;
        Bt[(d4 * 4 + 0) * PB + n] = pf[it].x;
        Bt[(d4 * 4 + 1) * PB + n] = pf[it].y;
        Bt[(d4 * 4 + 2) * PB + n] = pf[it].z;
        Bt[(d4 * 4 + 3) * PB + n] = pf[it].w;
    }
    __syncthreads();

    const int ty = tid >> 4;          // 0..31
    const int tx = tid & 15;          // 0..15
    const int r0 = ty * 8;            // 8 contiguous rows
    const int c0 = tx * 4;            // 4 contiguous cols

    for (int ct = 0; ct < NTILES; ++ct) {
        // ================= P1: scan(ct-1) | norms | prefetch | GEMM(ct) ======
        if (ct > 0) {
            const int cbase = (ct - 1) * TN + sh * 32;
            #pragma unroll 4
            for (int c = 0; c < 32; ++c) {
                float v = drow[c];
                if (v < tau) {                    // strict <: stable ties
                    int pos = KNN - 1;
                    while (pos > 0 && tv[pos - 1] > v) {
                        tv[pos] = tv[pos - 1];
                        ti[pos] = ti[pos - 1];
                        --pos;
                    }
                    tv[pos] = v;
                    ti[pos] = cbase + c;
                    tau = tv[KNN - 1];
                }
            }
        }
        if (tid < TM && ct == 0) {            // row norms once
            float s = 0.f;
            #pragma unroll
            for (int d = 0; d < DD; ++d) { float a = At[d * PA + tid]; s = fmaf(a, a, s); }
            x2r[tid] = s;
        }
        if (tid < TN) {                        // candidate norms for this tile
            float s = 0.f;
            #pragma unroll
            for (int d = 0; d < DD; ++d) { float b = Bt[d * PB + tid]; s = fmaf(b, b, s); }
            x2c[tid] = s;
        }
        // prefetch next B tile (hidden under GEMM)
        if (ct + 1 < NTILES) {
            const int col0n = (ct + 1) * TN;
            #pragma unroll
            for (int it = 0; it < 2; ++it) {
                int idx = it * NTHREADS + tid;
                int n   = idx & 63;
                int d4  = idx >> 6;
                pf[it] = *reinterpret_cast<const float4*>(xb + (size_t)(col0n + n) * DD + d4 * 4);
            }
        }

        // ---- 256x64x64 GEMM, 8x4 micro-tile, packed f32x2 (rows paired) ----
        ull acc[4][4];
        #pragma unroll
        for (int ip = 0; ip < 4; ++ip)
            #pragma unroll
            for (int j = 0; j < 4; ++j) acc[ip][j] = 0ULL;

        #pragma unroll 4
        for (int k = 0; k < DD; ++k) {
            ulonglong2 a01 = *reinterpret_cast<const ulonglong2*>(&At[k * PA + r0]);
            ulonglong2 a23 = *reinterpret_cast<const ulonglong2*>(&At[k * PA + r0 + 4]);
            float4 bv = *reinterpret_cast<const float4*>(&Bt[k * PB + c0]);
            ull ap[4] = {a01.x, a01.y, a23.x, a23.y};
            float bs[4] = {bv.x, bv.y, bv.z, bv.w};
            #pragma unroll
            for (int j = 0; j < 4; ++j) {
                ull b2 = splat2(bs[j]);
                #pragma unroll
                for (int ip = 0; ip < 4; ++ip)
                    acc[ip][j] = ffma2(ap[ip], b2, acc[ip][j]);
            }
        }
        __syncthreads();   // GEMM reads of Bt done; x2c (and x2r) visible

        // ================= P2: epilogue -> Dt | store prefetched Bt ==========
        {
            float xc[4];
            #pragma unroll
            for (int j = 0; j < 4; ++j) xc[j] = x2c[c0 + j];
            #pragma unroll
            for (int ip = 0; ip < 4; ++ip) {
                int ra = r0 + ip * 2;
                float xra = x2r[ra], xrb = x2r[ra + 1];
                #pragma unroll
                for (int j = 0; j < 4; ++j) {
                    // t - 2*dot via fma: rounds identically to the reference
                    Dt[ra * PD + c0 + j]       = fmaf(-2.f, lane_lo(acc[ip][j]), xra + xc[j]);
                    Dt[(ra + 1) * PD + c0 + j] = fmaf(-2.f, lane_hi(acc[ip][j]), xrb + xc[j]);
                }
            }
        }
        if (ct + 1 < NTILES) {
            #pragma unroll
            for (int it = 0; it < 2; ++it) {
                int idx = it * NTHREADS + tid;
                int n   = idx & 63;
                int d4  = idx >> 6;
                Bt[(d4 * 4 + 0) * PB + n] = pf[it].x;
                Bt[(d4 * 4 + 1) * PB + n] = pf[it].y;
                Bt[(d4 * 4 + 2) * PB + n] = pf[it].z;
                Bt[(d4 * 4 + 3) * PB + n] = pf[it].w;
            }
        }
        __syncthreads();
    }

    // ---- final scan (last tile) ----
    {
        const int cbase = (NTILES - 1) * TN + sh * 32;
        #pragma unroll 4
        for (int c = 0; c < 32; ++c) {
            float v = drow[c];
            if (v < tau) {
                int pos = KNN - 1;
                while (pos > 0 && tv[pos - 1] > v) {
                    tv[pos] = tv[pos - 1];
                    ti[pos] = ti[pos - 1];
                    --pos;
                }
                tv[pos] = v;
                ti[pos] = cbase + c;
                tau = tv[KNN - 1];
            }
        }
    }
    __syncthreads();   // all lists finalized in smem

    // ---- merge the two half-lists per row (stable: ties -> lower index) ----
    if (tid < TM) {
        const int row = tid;
        const float* v0 = &topv[(row * 2 + 0) * PL];
        const float* v1 = &topv[(row * 2 + 1) * PL];
        const int*   i0 = &topi[(row * 2 + 0) * PL];
        const int*   i1 = &topi[(row * 2 + 1) * PL];
        int p0 = 0, p1 = 0;
        const int gid  = batch * MP + row0 + row;
        const int off  = batch * MP;
        const int base = gid * KNN;
        #pragma unroll
        for (int t = 0; t < KNN; ++t) {
            float a = (p0 < KNN) ? v0[p0] : __int_as_float(0x7f800000);
            float b = (p1 < KNN) ? v1[p1] : __int_as_float(0x7f800000);
            int   ia = (p0 < KNN) ? i0[p0] : 0x7fffffff;
            int   ib = (p1 < KNN) ? i1[p1] : 0x7fffffff;
            bool take0 = (a < b) || (a == b && ia < ib);
            int sel = take0 ? ia : ib;
            if (take0) ++p0; else ++p1;
            out[base + t] = (float)(sel + off);
        }
        if (write_dst) {
            float fgid = (float)gid;
            #pragma unroll
            for (int t = 0; t < KNN; ++t) out[NEDGES + base + t] = fgid;
        }
    }
}

extern "C" void kernel_launch(void* const* d_in, const int* in_sizes, int n_in,
                              void* d_out, int out_size) {
    // Bind x = largest input (robust to ordering and element/byte units).
    const float* x = (const float*)d_in[0];
    long long best_sz = -1;
    for (int i = 0; i < n_in; ++i) {
        if ((long long)in_sizes[i] > best_sz) {
            best_sz = in_sizes[i];
            x = (const float*)d_in[i];
        }
    }
    const int write_dst = (out_size >= 2 * NEDGES);

    cudaFuncSetAttribute(knn_topk_kernel,
                         cudaFuncAttributeMaxDynamicSharedMemorySize, SMEM_BYTES);
    knn_topk_kernel<<<NB * (MP / TM), NTHREADS, SMEM_BYTES>>>(x, (float*)d_out, write_dst);
}

// round 15
// speedup vs baseline: 1.1465x; 1.0447x over previous
#include <cuda_runtime.h>
#include <cstdint>

// Problem constants (fixed: N=4, M=8192, D=64, k=16)
#define NB 4
#define MP 8192
#define DD 64
#define KNN 16
#define TM 128
#define TN 128
#define NTILES (MP / TN)         // 64
#define NTHREADS 256
#define NEDGES (NB * MP * KNN)   // 524288

// smem byte offsets
#define SO_A   0                          // 3 splits x 128x64 bf16 = 49152
#define SO_B   49152                      // 2 bufs x 3 x 16384 = 98304
#define SO_D   147456                     // 128 x 134 f32 = 68608
#define PD     134
#define SO_X2R (SO_D + TM * PD * 4)       // 216064
#define SO_X2C (SO_X2R + 512)             // 216576 (2 bufs x 128 f32)
#define SMEM_BYTES (SO_X2C + 1024)        // 217600

__device__ unsigned short g_hi [NB * MP * DD];
__device__ unsigned short g_mid[NB * MP * DD];
__device__ unsigned short g_lo [NB * MP * DD];
__device__ float g_x2[NB * MP];

// round-to-nearest-even f32 -> bf16 bits (finite inputs)
__device__ __forceinline__ unsigned short rnbf(float v) {
    unsigned u = __float_as_uint(v);
    return (unsigned short)((u + 0x7fffu + ((u >> 16) & 1u)) >> 16);
}

// ---- prep: bf16 3-way split + squared norms ----
__global__ __launch_bounds__(256)
void prep_kernel(const float* __restrict__ x) {
    int t = blockIdx.x * 256 + threadIdx.x;      // 0..131071
    int p = t >> 2, c = t & 3;
    const float* src = x + (size_t)p * DD + c * 16;
    unsigned wh[8], wm[8], wl[8];
    #pragma unroll
    for (int j = 0; j < 8; ++j) {
        float v0 = src[2 * j], v1 = src[2 * j + 1];
        unsigned short h0 = rnbf(v0);
        float r0 = v0 - __uint_as_float((unsigned)h0 << 16);
        unsigned short m0 = rnbf(r0);
        unsigned short l0 = rnbf(r0 - __uint_as_float((unsigned)m0 << 16));
        unsigned short h1 = rnbf(v1);
        float r1 = v1 - __uint_as_float((unsigned)h1 << 16);
        unsigned short m1 = rnbf(r1);
        unsigned short l1 = rnbf(r1 - __uint_as_float((unsigned)m1 << 16));
        wh[j] = (unsigned)h0 | ((unsigned)h1 << 16);
        wm[j] = (unsigned)m0 | ((unsigned)m1 << 16);
        wl[j] = (unsigned)l0 | ((unsigned)l1 << 16);
    }
    size_t base = (size_t)p * DD + c * 16;
    *(uint4*)(g_hi  + base)     = make_uint4(wh[0], wh[1], wh[2], wh[3]);
    *(uint4*)(g_hi  + base + 8) = make_uint4(wh[4], wh[5], wh[6], wh[7]);
    *(uint4*)(g_mid + base)     = make_uint4(wm[0], wm[1], wm[2], wm[3]);
    *(uint4*)(g_mid + base + 8) = make_uint4(wm[4], wm[5], wm[6], wm[7]);
    *(uint4*)(g_lo  + base)     = make_uint4(wl[0], wl[1], wl[2], wl[3]);
    *(uint4*)(g_lo  + base + 8) = make_uint4(wl[4], wl[5], wl[6], wl[7]);

    if (t < NB * MP) {
        const float4* q = reinterpret_cast<const float4*>(x + (size_t)t * DD);
        float s = 0.f;
        #pragma unroll
        for (int i = 0; i < 16; ++i) {
            float4 v = q[i];
            s = fmaf(v.x, v.x, s); s = fmaf(v.y, v.y, s);
            s = fmaf(v.z, v.z, s); s = fmaf(v.w, v.w, s);
        }
        g_x2[t] = s;
    }
}

__device__ __forceinline__ void cp16(uint32_t dst, const void* src) {
    asm volatile("cp.async.cg.shared.global [%0], [%1], 16;" :: "r"(dst), "l"(src));
}
__device__ __forceinline__ void ldsm_x4(uint32_t* r, uint32_t a) {
    asm volatile("ldmatrix.sync.aligned.m8n8.x4.shared.b16 {%0,%1,%2,%3}, [%4];"
        : "=r"(r[0]), "=r"(r[1]), "=r"(r[2]), "=r"(r[3]) : "r"(a));
}
__device__ __forceinline__ void ldsm_x2(uint32_t* r, uint32_t a) {
    asm volatile("ldmatrix.sync.aligned.m8n8.x2.shared.b16 {%0,%1}, [%2];"
        : "=r"(r[0]), "=r"(r[1]) : "r"(a));
}
__device__ __forceinline__ void mma16816(float* d, const uint32_t* a, const uint32_t* b) {
    asm volatile("mma.sync.aligned.m16n8k16.row.col.f32.bf16.bf16.f32 "
        "{%0,%1,%2,%3}, {%4,%5,%6,%7}, {%8,%9}, {%0,%1,%2,%3};"
        : "+f"(d[0]), "+f"(d[1]), "+f"(d[2]), "+f"(d[3])
        : "r"(a[0]), "r"(a[1]), "r"(a[2]), "r"(a[3]), "r"(b[0]), "r"(b[1]));
}

__global__ __launch_bounds__(NTHREADS, 1)
void knn_mma_kernel(float* __restrict__ out, int write_dst) {
    extern __shared__ char smc[];
    const uint32_t su = (uint32_t)__cvta_generic_to_shared(smc);
    float* Dt  = (float*)(smc + SO_D);
    float* x2r = (float*)(smc + SO_X2R);
    float* xcs = (float*)(smc + SO_X2C);

    const int tid = threadIdx.x, warp = tid >> 5, lane = tid & 31;
    const int batch = blockIdx.x >> 6, rtile = blockIdx.x & 63;
    const int row0 = rtile * TM, pbase = batch * MP;
    const unsigned short* gs[3] = {g_hi, g_mid, g_lo};

    // ---- prologue: cp.async A (3 splits), B tile 0, norms ----
    #pragma unroll
    for (int it = 0; it < 12; ++it) {
        int idx = it * NTHREADS + tid, s = idx >> 10, rem = idx & 1023;
        int r = rem >> 3, ch = rem & 7;
        cp16(su + SO_A + s * 16384 + r * 128 + ((ch ^ (r & 7)) << 4),
             gs[s] + ((size_t)(pbase + row0 + r) * DD + ch * 8));
    }
    #pragma unroll
    for (int it = 0; it < 12; ++it) {
        int idx = it * NTHREADS + tid, s = idx >> 10, rem = idx & 1023;
        int n = rem >> 3, ch = rem & 7;
        cp16(su + SO_B + s * 16384 + n * 128 + ((ch ^ (n & 7)) << 4),
             gs[s] + ((size_t)(pbase + n) * DD + ch * 8));
    }
    if (tid < 32) {
        cp16(su + SO_X2R + tid * 16, g_x2 + pbase + row0 + tid * 4);
        cp16(su + SO_X2C + tid * 16, g_x2 + pbase + tid * 4);
    }
    asm volatile("cp.async.commit_group;");
    asm volatile("cp.async.wait_group 0;");
    __syncthreads();

    const int WR = (warp >> 2) * 64, WC = (warp & 3) * 32;
    // ldmatrix lane addressing
    const int a_row = (lane & 7) + ((lane >> 3) & 1) * 8;  // within m16 tile
    const int a_cs  = lane >> 4;                           // k-chunk select 0/1
    const int l2    = lane & 15;
    const int b_nr  = l2 & 7;                              // within n8 tile
    const int b_cs  = l2 >> 3;

    // scan: 2 threads per row, 64 cols each
    const int srow = tid >> 1, sh = tid & 1;
    const float* drow = Dt + srow * PD + sh * 64;

    float best[KNN]; int bidx[KNN];
    #pragma unroll
    for (int i = 0; i < KNN; ++i) { best[i] = __int_as_float(0x7f800000); bidx[i] = 0; }
    float tau = __int_as_float(0x7f800000);

    for (int ct = 0; ct < NTILES; ++ct) {
        const int b = ct & 1;
        // prefetch next B + its norms (cp.async, overlaps everything below)
        if (ct + 1 < NTILES) {
            const int col0n = (ct + 1) * TN;
            #pragma unroll
            for (int it = 0; it < 12; ++it) {
                int idx = it * NTHREADS + tid, s = idx >> 10, rem = idx & 1023;
                int n = rem >> 3, ch = rem & 7;
                cp16(su + SO_B + (1 - b) * 49152 + s * 16384 + n * 128 + ((ch ^ (n & 7)) << 4),
                     gs[s] + ((size_t)(pbase + col0n + n) * DD + ch * 8));
            }
            if (tid < 32)
                cp16(su + SO_X2C + (1 - b) * 512 + tid * 16, g_x2 + pbase + col0n + tid * 4);
            asm volatile("cp.async.commit_group;");
        }

        // ---- MMA: 128x128x64, bf16x6 (hh,hm,mh,mm,hl,lh) ----
        float acc[4][4][4];
        #pragma unroll
        for (int mi = 0; mi < 4; ++mi)
            #pragma unroll
            for (int ni = 0; ni < 4; ++ni)
                #pragma unroll
                for (int q = 0; q < 4; ++q) acc[mi][ni][q] = 0.f;

        const uint32_t abase = su + SO_A;
        const uint32_t bbase = su + SO_B + b * 49152;
        #pragma unroll
        for (int kc = 0; kc < 4; ++kc) {
            uint32_t af[3][4][4], bf[3][4][2];
            #pragma unroll
            for (int s = 0; s < 3; ++s) {
                #pragma unroll
                for (int mi = 0; mi < 4; ++mi) {
                    int row = WR + mi * 16 + a_row;
                    ldsm_x4(af[s][mi], abase + s * 16384 + row * 128
                                     + (((2 * kc + a_cs) ^ (row & 7)) << 4));
                }
                #pragma unroll
                for (int ni = 0; ni < 4; ++ni) {
                    int n = WC + ni * 8 + b_nr;
                    ldsm_x2(bf[s][ni], bbase + s * 16384 + n * 128
                                     + (((2 * kc + b_cs) ^ (n & 7)) << 4));
                }
            }
            const int SA[6] = {0, 0, 1, 1, 0, 2};
            const int SB[6] = {0, 1, 0, 1, 2, 0};
            #pragma unroll
            for (int t = 0; t < 6; ++t)
                #pragma unroll
                for (int mi = 0; mi < 4; ++mi)
                    #pragma unroll
                    for (int ni = 0; ni < 4; ++ni)
                        mma16816(acc[mi][ni], af[SA[t]][mi], bf[SB[t]][ni]);
        }

        // ---- scan previous tile's Dt ----
        if (ct > 0) {
            const int cbase = (ct - 1) * TN + sh * 64;
            #pragma unroll 4
            for (int c = 0; c < 64; ++c) {
                float v = drow[c];
                if (v < tau) {                       // strict <: stable ties
                    best[KNN - 1] = v;
                    bidx[KNN - 1] = cbase + c;
                    #pragma unroll
                    for (int u = KNN - 1; u > 0; --u) {
                        if (best[u] < best[u - 1]) {
                            float tv = best[u]; best[u] = best[u - 1]; best[u - 1] = tv;
                            int   ti = bidx[u]; bidx[u] = bidx[u - 1]; bidx[u - 1] = ti;
                        }
                    }
                    tau = best[KNN - 1];
                }
            }
        }
        __syncthreads();    // scans done -> Dt free for overwrite

        // ---- epilogue: d2 -> Dt ----
        {
            const float* xc = xcs + b * 128;
            #pragma unroll
            for (int mi = 0; mi < 4; ++mi) {
                int rl = WR + mi * 16 + (lane >> 2);
                float xrl = x2r[rl], xrh = x2r[rl + 8];
                #pragma unroll
                for (int ni = 0; ni < 4; ++ni) {
                    int col = WC + ni * 8 + (lane & 3) * 2;
                    float xc0 = xc[col], xc1 = xc[col + 1];
                    float2 lo, hi;
                    lo.x = fmaf(-2.f, acc[mi][ni][0], xrl + xc0);
                    lo.y = fmaf(-2.f, acc[mi][ni][1], xrl + xc1);
                    hi.x = fmaf(-2.f, acc[mi][ni][2], xrh + xc0);
                    hi.y = fmaf(-2.f, acc[mi][ni][3], xrh + xc1);
                    *(float2*)(Dt + rl * PD + col)       = lo;
                    *(float2*)(Dt + (rl + 8) * PD + col) = hi;
                }
            }
        }
        if (ct + 1 < NTILES) asm volatile("cp.async.wait_group 0;");
        __syncthreads();    // Dt(ct) visible; B(ct+1) landed
    }

    // ---- final scan (last tile) ----
    {
        const int cbase = (NTILES - 1) * TN + sh * 64;
        #pragma unroll 4
        for (int c = 0; c < 64; ++c) {
            float v = drow[c];
            if (v < tau) {
                best[KNN - 1] = v;
                bidx[KNN - 1] = cbase + c;
                #pragma unroll
                for (int u = KNN - 1; u > 0; --u) {
                    if (best[u] < best[u - 1]) {
                        float tv = best[u]; best[u] = best[u - 1]; best[u - 1] = tv;
                        int   ti = bidx[u]; bidx[u] = bidx[u - 1]; bidx[u - 1] = ti;
                    }
                }
                tau = best[KNN - 1];
            }
        }
    }
    __syncthreads();   // A region no longer needed -> merge scratch

    float* mv  = (float*)(smc + SO_A);              // 256 lists x 16, stride 17
    int*   mi_ = (int*)(smc + SO_A + 18432);
    #pragma unroll
    for (int j = 0; j < KNN; ++j) {
        mv [tid * 17 + j] = best[j];
        mi_[tid * 17 + j] = bidx[j];
    }
    __syncthreads();

    // ---- merge two half-lists per row (stable: ties -> lower index) ----
    if (tid < TM) {
        const float* v0 = &mv [(2 * tid + 0) * 17];
        const float* v1 = &mv [(2 * tid + 1) * 17];
        const int*   i0 = &mi_[(2 * tid + 0) * 17];
        const int*   i1 = &mi_[(2 * tid + 1) * 17];
        int p0 = 0, p1 = 0;
        const int gid  = pbase + row0 + tid;
        const int base = gid * KNN;
        #pragma unroll
        for (int t = 0; t < KNN; ++t) {
            float a = (p0 < KNN) ? v0[p0] : __int_as_float(0x7f800000);
            float bb = (p1 < KNN) ? v1[p1] : __int_as_float(0x7f800000);
            int   ia = (p0 < KNN) ? i0[p0] : 0x7fffffff;
            int   ib = (p1 < KNN) ? i1[p1] : 0x7fffffff;
            bool take0 = (a < bb) || (a == bb && ia < ib);
            int sel = take0 ? ia : ib;
            if (take0) ++p0; else ++p1;
            out[base + t] = (float)(sel + pbase);
        }
        if (write_dst) {
            float fg = (float)gid;
            #pragma unroll
            for (int t = 0; t < KNN; ++t) out[NEDGES + base + t] = fg;
        }
    }
}

extern "C" void kernel_launch(void* const* d_in, const int* in_sizes, int n_in,
                              void* d_out, int out_size) {
    // Bind x = largest input (robust to ordering and element/byte units).
    const float* x = (const float*)d_in[0];
    long long best_sz = -1;
    for (int i = 0; i < n_in; ++i) {
        if ((long long)in_sizes[i] > best_sz) {
            best_sz = in_sizes[i];
            x = (const float*)d_in[i];
        }
    }
    const int write_dst = (out_size >= 2 * NEDGES);

    prep_kernel<<<(NB * MP * 4) / 256, 256>>>(x);

    cudaFuncSetAttribute(knn_mma_kernel,
                         cudaFuncAttributeMaxDynamicSharedMemorySize, SMEM_BYTES);
    knn_mma_kernel<<<NB * (MP / TM), NTHREADS, SMEM_BYTES>>>((float*)d_out, write_dst);
}